// round 14
// baseline (speedup 1.0000x reference)
#include <cuda_runtime.h>
#include <cuda_fp16.h>
#include <math.h>
#include <stdint.h>

// Problem constants
#define Bb 4
#define Lb 4096
#define Cb 512
#define Gb 4
#define GCb 128
#define Hb 16
#define HCb 32
#define Mb (Bb*Lb)        // 16384
#define NBg (Bb*Gb)       // 16

// ---------------- scratch (static device globals; no allocation) -------------
__device__ __half g_qh[Bb*Cb*Lb];                  // q fp16 [B,C,L] (attn only)
__device__ __half g_kh[Bb*Cb*Lb];                  // k fp16 [B,C,L] (attn only)
__device__ __half g_xh[Mb*Cb];                     // x fp16      [M,C]
__device__ __half g_sh[Mb*Cb];                     // xs fp16     [M,C]
__device__ __half g_oh[Mb*Cb];                     // o_pre fp16  [M,C]
__device__ __half g_w16[4][Cb*Cb];                 // weights fp16
__device__ float g_weff[GCb*5];
__device__ float g_ybias[Gb*5];
__device__ float g_bias2[2];
__device__ float g_y[NBg*5*Lb];                    // offset conv projections
__device__ float g_attn[64*HCb*HCb];               // softmaxed, TRANSPOSED [bh][j][i]

// ---------------- small helpers ----------------------------------------------
__device__ __forceinline__ uint32_t smem_to_u32(const void* p) {
    uint32_t a;
    asm("{ .reg .u64 t; cvta.to.shared.u64 t, %1; cvt.u32.u64 %0, t; }" : "=r"(a) : "l"(p));
    return a;
}

#define LDM4(r, a) \
    asm volatile("ldmatrix.sync.aligned.m8n8.x4.shared.b16 {%0,%1,%2,%3}, [%4];" \
        : "=r"((r)[0]), "=r"((r)[1]), "=r"((r)[2]), "=r"((r)[3]) : "r"(a))

__device__ __forceinline__ void mma16816(float* d, const uint32_t* a, const uint32_t* b) {
    asm volatile("mma.sync.aligned.m16n8k16.row.col.f32.f16.f16.f32 "
        "{%0,%1,%2,%3}, {%4,%5,%6,%7}, {%8,%9}, {%0,%1,%2,%3};"
        : "+f"(d[0]), "+f"(d[1]), "+f"(d[2]), "+f"(d[3])
        : "r"(a[0]), "r"(a[1]), "r"(a[2]), "r"(a[3]), "r"(b[0]), "r"(b[1]));
}

__device__ __forceinline__ void cp_async16(uint32_t dst, const void* src) {
    asm volatile("cp.async.cg.shared.global [%0], [%1], 16;" :: "r"(dst), "l"(src));
}
#define CP_COMMIT()  asm volatile("cp.async.commit_group;" ::: "memory")
#define CP_WAIT(n)   asm volatile("cp.async.wait_group %0;" :: "n"(n) : "memory")

__device__ __forceinline__ uint32_t swz(uint32_t off) { return off ^ ((off >> 3) & 0x70); }

// ---------------- merged preprocessing (x->fp16, W->fp16, weff+ybias) --------
// blocks [0,8192): convert_x; [8192,9216): convert_w (4x256); block 9216: weff
__global__ __launch_bounds__(256)
void preproc_kernel(const float* __restrict__ x,
                    const float* __restrict__ W0, const float* __restrict__ W1,
                    const float* __restrict__ W2, const float* __restrict__ W3,
                    const float* __restrict__ Woff1, const float* __restrict__ boff1,
                    const float* __restrict__ Woff2, const float* __restrict__ boff2,
                    const float* __restrict__ bq)
{
    const int blk = blockIdx.x;
    const int tid = threadIdx.x;
    if (blk < 8192) {
        size_t i = (size_t)blk*256 + tid;              // Mb*Cb/4 items
        float4 v = ((const float4*)x)[i];
        __half2 p0; p0.x = __float2half(v.x); p0.y = __float2half(v.y);
        __half2 p1; p1.x = __float2half(v.z); p1.y = __float2half(v.w);
        ((__half2*)g_xh)[2*i]   = p0;
        ((__half2*)g_xh)[2*i+1] = p1;
    } else if (blk < 9216) {
        const int r = blk - 8192;
        const int w = r >> 8;
        const float* W = (w==0) ? W0 : (w==1) ? W1 : (w==2) ? W2 : W3;
        size_t i = (size_t)(r & 255)*256 + tid;        // Cb*Cb/4 items
        float4 v = ((const float4*)W)[i];
        __half2 p0; p0.x = __float2half(v.x); p0.y = __float2half(v.y);
        __half2 p1; p1.x = __float2half(v.z); p1.y = __float2half(v.w);
        ((__half2*)g_w16[w])[2*i]   = p0;
        ((__half2*)g_w16[w])[2*i+1] = p1;
    } else {
        for (int i = tid; i < GCb*5; i += 256) {
            int dp = i / 5, t = i % 5;
            float s = 0.f;
            #pragma unroll 4
            for (int d = 0; d < GCb; d++)
                s += Woff2[d] * Woff1[(d*GCb + dp)*5 + t];
            g_weff[i] = s;
        }
        if (tid == 0) {
            float s = boff2[0];
            for (int d = 0; d < GCb; d++) s += Woff2[d]*boff1[d];
            g_bias2[0] = s;
            g_bias2[1] = boff2[0];
        }
        __syncthreads();   // g_weff (written by this block) visible
        if (tid < Gb*5) {
            int g = tid / 5, t = tid % 5;
            float s = 0.f;
            for (int d = 0; d < GCb; d++)
                s += g_weff[d*5 + t] * bq[g*GCb + d];
            g_ybias[tid] = s;
        }
    }
}

// ---------------- mma.sync GEMM: out[m,n] = sum_k A[m,k]*W[n,k] --------------
// A,W fp16. CTA tile 128x128, 256 thr (8 warps, 2x4), warp tile 64x32,
// K chunks of 64, 3-stage cp.async ring, ONE sync/chunk, 2 CTAs/SM.
// o_sel: 0 = g_qh fp16 [B,C,L]+bias AND offset-conv projections y -> g_y;
//        1 = g_kh fp16 [B,C,L]+bias;
//        2 = fused attn·V epilogue -> g_oh fp16 [M,C];
//        3 = row-major [M,C] + bias (final output).
#define KCHUNK 64
#define TILE_B 16384            // one 128x64 fp16 tile
#define STAGE_B (2*TILE_B)      // A, W

__global__ __launch_bounds__(256, 2)
void mma_gemm(int a_sel, int w_idx, int o_sel,
              const float* __restrict__ bias,
              const float* __restrict__ rpb,
              float* __restrict__ Or)
{
    extern __shared__ __align__(1024) char smem[];
    const uint32_t su = smem_to_u32(smem);
    const int tid = threadIdx.x;
    const int wid = tid >> 5, lane = tid & 31;
    const int bm = blockIdx.x, bn = blockIdx.y;

    const __half* A = (a_sel==0) ? g_xh : (a_sel==1) ? g_sh : g_oh;
    const __half* srcs[2] = {A, g_w16[w_idx]};

    // ---- stage loader: 2 tiles x 1024 16B-chunks, 8 cp.async per thread ----
    auto load_stage = [&](int s, int buf) {
        const int k0 = s*KCHUNK;
        #pragma unroll
        for (int t = 0; t < 2; t++) {
            const __half* src = srcs[t];
            const int rbase = ((t == 0) ? bm : bn) * 128;
            const uint32_t tb = su + buf*STAGE_B + t*TILE_B;
            #pragma unroll
            for (int i = 0; i < 4; i++) {
                int cid = tid + i*256;
                int row = cid >> 3, cu = cid & 7;
                const void* g = src + (size_t)(rbase + row)*Cb + k0 + cu*8;
                cp_async16(tb + swz((uint32_t)(row*128 + cu*16)), g);
            }
        }
        CP_COMMIT();
    };

    // ---- per-lane fragment addressing (warp tile 64x32) ----
    const int warp_m = wid >> 2;          // 0..1 (64 rows each)
    const int warp_n = wid & 3;           // 0..3 (32 cols each)
    const int lr = lane & 7;
    uint32_t aRowOff[4];
    #pragma unroll
    for (int mt = 0; mt < 4; mt++)
        aRowOff[mt] = (uint32_t)((warp_m*64 + mt*16 + lr + ((lane>>3)&1)*8) * 128);
    const uint32_t aC = (uint32_t)(lane >> 4);
    uint32_t bRowOff[2];
    #pragma unroll
    for (int nh = 0; nh < 2; nh++)
        bRowOff[nh] = (uint32_t)((warp_n*32 + nh*16 + lr + (lane>>4)*8) * 128);
    const uint32_t bC = (uint32_t)((lane >> 3) & 1);

    float acc[4][4][4];
    #pragma unroll
    for (int mt = 0; mt < 4; mt++)
        #pragma unroll
        for (int nt = 0; nt < 4; nt++)
            #pragma unroll
            for (int c = 0; c < 4; c++) acc[mt][nt][c] = 0.f;

    // ---- 3-stage ring: buffers s%3; one barrier per chunk ----
    load_stage(0, 0);
    load_stage(1, 1);

    #pragma unroll 1
    for (int kc = 0; kc < 8; kc++) {
        if (kc < 7) { CP_WAIT(1); } else { CP_WAIT(0); }
        __syncthreads();
        if (kc + 2 < 8) load_stage(kc + 2, (kc + 2) % 3);

        const uint32_t sb = su + (uint32_t)(kc % 3)*STAGE_B;
        #pragma unroll
        for (int ks = 0; ks < 4; ks++) {
            uint32_t ah[4][4], bf[2][4];
            #pragma unroll
            for (int mt = 0; mt < 4; mt++) {
                uint32_t off = swz(aRowOff[mt] + (ks*2 + aC)*16);
                LDM4(ah[mt], sb + off);
            }
            #pragma unroll
            for (int nh = 0; nh < 2; nh++) {
                uint32_t off = swz(bRowOff[nh] + (ks*2 + bC)*16);
                LDM4(bf[nh], sb + TILE_B + off);
            }
            #pragma unroll
            for (int mt = 0; mt < 4; mt++)
                #pragma unroll
                for (int nt = 0; nt < 4; nt++)
                    mma16816(acc[mt][nt], ah[mt], &bf[nt >> 1][(nt & 1)*2]);
        }
    }
    __syncthreads();   // all compute done before epilogue reuses smem

    const int g = lane >> 2, t4 = lane & 3;

    if (o_sel == 2) {
        // ======== fused attn·V epilogue (4 heads per CTA) ========
        float* v_s  = (float*)smem;                 // [128 c][129] floats
        float* at_s = (float*)smem + 128*129;       // attn_t 4 heads x 32 x 32
        #pragma unroll
        for (int mt = 0; mt < 4; mt++)
            #pragma unroll
            for (int nt = 0; nt < 4; nt++)
                #pragma unroll
                for (int c = 0; c < 4; c++) {
                    int ml = warp_m*64 + mt*16 + g + (c >> 1)*8;
                    int nl = warp_n*32 + nt*8 + 2*t4 + (c & 1);
                    v_s[nl*129 + ml] = acc[mt][nt][c];
                }
        const int bidx  = (bm*128) >> 12;
        const int lbase = (bm*128) & 4095;
        const float* asrc = g_attn + ((size_t)bidx*16 + bn*4)*1024;
        for (int i = tid; i < 4096; i += 256) at_s[i] = asrc[i];
        __syncthreads();
        #pragma unroll 1
        for (int r = 0; r < 64; r++) {
            int idx = tid + r*256;
            int c = idx >> 7, l = idx & 127;
            v_s[c*129 + l] += bias[bn*128 + c]
                            + rpb[(size_t)(bn*128 + c)*Lb + lbase + l];
        }
        __syncthreads();
        #pragma unroll 1
        for (int task = wid; task < 64; task += 8) {
            int lb = task >> 2, hh = task & 3;
            float areg[32];
            #pragma unroll
            for (int j = 0; j < 32; j++)
                areg[j] = at_s[(hh*32 + j)*32 + lane];   // attn_t[j][i=lane]
            #pragma unroll
            for (int ll = 0; ll < 8; ll++) {
                int l = lb*8 + ll;
                float o = 0.f;
                #pragma unroll
                for (int j = 0; j < 32; j++)
                    o += areg[j] * v_s[(hh*32 + j)*129 + l];
                size_t oidx = ((size_t)bidx*Lb + lbase + l)*Cb + bn*128 + hh*32 + lane;
                g_oh[oidx] = __float2half(o);
            }
        }
        return;
    }

    // ======== standard epilogue: stage warp tile (64x32) into padded smem ====
    float* sacc = (float*)smem + (size_t)wid*(64*33);
    #pragma unroll
    for (int mt = 0; mt < 4; mt++)
        #pragma unroll
        for (int nt = 0; nt < 4; nt++)
            #pragma unroll
            for (int c = 0; c < 4; c++) {
                int ml = mt*16 + g + (c >> 1)*8;
                int nl = nt*8 + 2*t4 + (c & 1);
                sacc[ml*33 + nl] = acc[mt][nt][c];
            }
    __syncwarp();

    const int bidx = (bm*128) >> 12;
    const int lbase = (bm*128) & 4095;

    if (o_sel == 0) {
        // q fp16 store (bias fused)
        const int lwarp = lbase + warp_m*64;
        #pragma unroll 1
        for (int n = 0; n < 32; n++) {
            const int nglob = bn*128 + warp_n*32 + n;
            const float bv = bias[nglob];
            #pragma unroll
            for (int h2 = 0; h2 < 2; h2++) {
                const int ml = h2*32 + lane;
                g_qh[((size_t)bidx*Cb + nglob)*Lb + lwarp + ml]
                    = __float2half(sacc[ml*33 + n] + bv);
            }
        }
        // ---- offset-conv projections: y[t][l] = sum_d Weff[d,t]*qraw[d,l] ----
        float* weff_s = (float*)smem + 8*64*33;     // 640 floats
        float* py     = weff_s + 640;               // 8 warps x 5 x 64
        for (int i = tid; i < 640; i += 256) weff_s[i] = g_weff[i];
        __syncthreads();
        #pragma unroll
        for (int h2 = 0; h2 < 2; h2++) {
            const int ml = h2*32 + lane;
            float y0=0.f, y1=0.f, y2=0.f, y3=0.f, y4=0.f;
            #pragma unroll 4
            for (int d = 0; d < 32; d++) {
                float qv = sacc[ml*33 + d];
                const float* wr = weff_s + (warp_n*32 + d)*5;
                y0 += qv*wr[0]; y1 += qv*wr[1]; y2 += qv*wr[2];
                y3 += qv*wr[3]; y4 += qv*wr[4];
            }
            float* p = py + wid*320 + ml;
            p[0] = y0; p[64] = y1; p[128] = y2; p[192] = y3; p[256] = y4;
        }
        __syncthreads();
        // reduce over warp_n (4 partials) + ybias, write g_y
        for (int idx = tid; idx < 640; idx += 256) {
            int wm = idx / 320;
            int r  = idx % 320;              // t*64 + ml
            int t  = r >> 6;
            float y = py[(wm*4+0)*320 + r] + py[(wm*4+1)*320 + r]
                    + py[(wm*4+2)*320 + r] + py[(wm*4+3)*320 + r]
                    + g_ybias[bn*5 + t];
            int l = lbase + wm*64 + (r & 63);
            g_y[((size_t)(bidx*Gb + bn)*5 + t)*Lb + l] = y;
        }
        return;
    }

    if (o_sel == 1) {
        const int lwarp = lbase + warp_m*64;
        #pragma unroll 1
        for (int n = 0; n < 32; n++) {
            const int nglob = bn*128 + warp_n*32 + n;
            const float bv = bias[nglob];
            #pragma unroll
            for (int h2 = 0; h2 < 2; h2++) {
                const int ml = h2*32 + lane;
                g_kh[((size_t)bidx*Cb + nglob)*Lb + lwarp + ml]
                    = __float2half(sacc[ml*33 + n] + bv);
            }
        }
    } else {
        const int nglob = bn*128 + warp_n*32 + lane;
        const float bv = bias[nglob];
        #pragma unroll 1
        for (int ml = 0; ml < 64; ml++) {
            const int m = bm*128 + warp_m*64 + ml;
            Or[(size_t)m*Cb + nglob] = sacc[ml*33 + lane] + bv;
        }
    }
}

// ---------------- 1-D bilinear grid sample w/ inline offset ------------------
__global__ __launch_bounds__(256)
void gridsample_kernel()
{
    const int bl = blockIdx.x;
    const int b  = bl >> 12;
    const int l  = bl & 4095;

    const int c2 = threadIdx.x;        // half2 index; channels 2*c2, 2*c2+1
    const int g  = c2 >> 6;            // warp-uniform
    const float* yb = g_y + (size_t)(b*Gb + g)*5*Lb;

    float accf;
    if (l >= 4) {
        accf = g_bias2[0];
        #pragma unroll
        for (int t = 0; t < 5; t++) accf += yb[(size_t)t*Lb + l - 4 + t];
    } else if (l >= 2) {
        accf = g_bias2[0];
        for (int t = 4 - l; t < 5; t++) accf += yb[(size_t)t*Lb + l - 4 + t];
    } else {
        accf = g_bias2[1];
    }
    const float off = tanhf(accf) * 5.0f;

    const float vgrid = (float)l + off;
    const float gy = 2.0f * vgrid / (float)(Lb + 4 - 1) - 1.0f;
    const float iy = ((gy + 1.0f) * (float)Lb - 1.0f) * 0.5f;
    const float fi0 = floorf(iy);
    const float w1 = iy - fi0;
    const int i0 = (int)fi0;
    const int i1 = i0 + 1;

    float2 f0 = make_float2(0.f, 0.f), f1 = make_float2(0.f, 0.f);
    if (i0 >= 0 && i0 < Lb)
        f0 = __half22float2(((const __half2*)(g_xh + ((size_t)b*Lb + i0)*Cb))[c2]);
    if (i1 >= 0 && i1 < Lb)
        f1 = __half22float2(((const __half2*)(g_xh + ((size_t)b*Lb + i1)*Cb))[c2]);
    const float w0 = 1.f - w1;
    __half2 r;
    r.x = __float2half(f0.x*w0 + f1.x*w1);
    r.y = __float2half(f0.y*w0 + f1.y*w1);
    ((__half2*)(g_sh + (size_t)bl*Cb))[c2] = r;
}

// ---------------- attention: logits (mma.sync) + softmax, one block per bh ---
// 8 warps x 512 L each, 3-buffer per-warp cp.async ring (no cross-warp sync in
// mainloop). Per-warp 32x32 fp32 partial -> smem; block reduce; softmax;
// write g_attn TRANSPOSED [bh][j][i].
#define QK_TILE 4096            // one 32x64 fp16 tile
#define QK_WSTAGE (6*QK_TILE)   // 3 ring slots x (q,k) = 24KB per warp
__global__ __launch_bounds__(256)
void attn_qk()
{
    extern __shared__ __align__(1024) char qsmem[];
    const uint32_t su = smem_to_u32(qsmem);
    const int tid = threadIdx.x;
    const int wid = tid >> 5, lane = tid & 31;
    const int bh = blockIdx.x;            // 0..63
    const int b = bh >> 4, h = bh & 15;
    const size_t base = ((size_t)b*Cb + h*HCb) * Lb;
    const __half* qb = g_qh + base;
    const __half* kb = g_kh + base;
    const int l0 = wid*512;

    const uint32_t wbase = su + (uint32_t)wid*QK_WSTAGE;

    auto load_chunk = [&](int ch) {
        const int lo = l0 + ch*64;
        const uint32_t tb = wbase + (uint32_t)(ch % 3)*(2*QK_TILE);
        #pragma unroll
        for (int i = 0; i < 8; i++) {
            int cid = lane + i*32;
            int row = cid >> 3, cu = cid & 7;
            uint32_t so = swz((uint32_t)(row*128 + cu*16));
            cp_async16(tb + so,           qb + (size_t)row*Lb + lo + cu*8);
            cp_async16(tb + QK_TILE + so, kb + (size_t)row*Lb + lo + cu*8);
        }
        CP_COMMIT();
    };

    const int lr = lane & 7;
    uint32_t aRowOff[2], bRowOff[2];
    #pragma unroll
    for (int mt = 0; mt < 2; mt++)
        aRowOff[mt] = (uint32_t)((mt*16 + lr + ((lane>>3)&1)*8) * 128);
    const uint32_t aC = (uint32_t)(lane >> 4);
    #pragma unroll
    for (int nh = 0; nh < 2; nh++)
        bRowOff[nh] = (uint32_t)((nh*16 + lr + (lane>>4)*8) * 128);
    const uint32_t bC = (uint32_t)((lane >> 3) & 1);

    float acc[2][4][4];
    #pragma unroll
    for (int mt = 0; mt < 2; mt++)
        #pragma unroll
        for (int nt = 0; nt < 4; nt++)
            #pragma unroll
            for (int c = 0; c < 4; c++) acc[mt][nt][c] = 0.f;

    load_chunk(0);
    load_chunk(1);

    #pragma unroll 1
    for (int ch = 0; ch < 8; ch++) {
        if (ch < 7) { CP_WAIT(1); } else { CP_WAIT(0); }
        __syncwarp();
        if (ch + 2 < 8) load_chunk(ch + 2);
        const uint32_t tb = wbase + (uint32_t)(ch % 3)*(2*QK_TILE);
        #pragma unroll
        for (int ks = 0; ks < 4; ks++) {
            uint32_t af[2][4], bf[2][4];
            #pragma unroll
            for (int mt = 0; mt < 2; mt++)
                LDM4(af[mt], tb + swz(aRowOff[mt] + (ks*2 + aC)*16));
            #pragma unroll
            for (int nh = 0; nh < 2; nh++)
                LDM4(bf[nh], tb + QK_TILE + swz(bRowOff[nh] + (ks*2 + bC)*16));
            #pragma unroll
            for (int mt = 0; mt < 2; mt++)
                #pragma unroll
                for (int nt = 0; nt < 4; nt++)
                    mma16816(acc[mt][nt], af[mt], &bf[nt >> 1][(nt & 1)*2]);
        }
    }

    // per-warp partial into its own staging region (mainloop done for this warp)
    float* part = (float*)(qsmem + (size_t)wid*QK_WSTAGE);
    const int g = lane >> 2, t4 = lane & 3;
    #pragma unroll
    for (int mt = 0; mt < 2; mt++)
        #pragma unroll
        for (int nt = 0; nt < 4; nt++)
            #pragma unroll
            for (int c = 0; c < 4; c++) {
                int ml = mt*16 + g + (c >> 1)*8;
                int nl = nt*8 + 2*t4 + (c & 1);
                part[ml*32 + nl] = acc[mt][nt][c];
            }
    __syncthreads();

    // reduce 8 partials -> ls (scaled logits); ls lives in free staging space
    float* ls = (float*)(qsmem + QK_TILE);   // bytes [4K,8K): warp0 slot1, now free
    const float* pbase = (const float*)qsmem;
    for (int i = tid; i < 1024; i += 256) {
        float v = 0.f;
        #pragma unroll
        for (int w = 0; w < 8; w++) v += pbase[(size_t)w*(QK_WSTAGE/4) + i];
        ls[i] = v * 0.044194173824159216f;   // 512^-0.5
    }
    __syncthreads();

    // softmax over j (row i = wid*4+r); write transposed attn [j][i]
    #pragma unroll
    for (int r = 0; r < 4; r++) {
        const int i = wid*4 + r;
        float v = ls[i*32 + lane];
        float mx = v;
        #pragma unroll
        for (int s = 16; s > 0; s >>= 1) mx = fmaxf(mx, __shfl_xor_sync(0xffffffffu, mx, s));
        float e = expf(v - mx);
        float sum = e;
        #pragma unroll
        for (int s = 16; s > 0; s >>= 1) sum += __shfl_xor_sync(0xffffffffu, sum, s);
        g_attn[(size_t)bh*1024 + lane*32 + i] = e / sum;
    }
}

// ---------------- launcher ---------------------------------------------------
extern "C" void kernel_launch(void* const* d_in, const int* in_sizes, int n_in,
                              void* d_out, int out_size)
{
    const float* x     = (const float*)d_in[0];
    const float* Wq    = (const float*)d_in[1];
    const float* bq    = (const float*)d_in[2];
    const float* Wk    = (const float*)d_in[3];
    const float* bk    = (const float*)d_in[4];
    const float* Wv    = (const float*)d_in[5];
    const float* bv    = (const float*)d_in[6];
    const float* Woff1 = (const float*)d_in[7];
    const float* boff1 = (const float*)d_in[8];
    const float* Woff2 = (const float*)d_in[9];
    const float* boff2 = (const float*)d_in[10];
    const float* rpb   = (const float*)d_in[11];
    const float* Wout  = (const float*)d_in[12];
    const float* bout  = (const float*)d_in[13];
    float* out = (float*)d_out;

    const int GSMEM = 3*STAGE_B;       // 98304 (>= all GEMM epilogues)
    const int QSMEM = 8*QK_WSTAGE;     // 196608
    cudaFuncSetAttribute(mma_gemm, cudaFuncAttributeMaxDynamicSharedMemorySize, GSMEM);
    cudaFuncSetAttribute(attn_qk,  cudaFuncAttributeMaxDynamicSharedMemorySize, QSMEM);

    dim3 ggrid(Mb/128, Cb/128);    // (128, 4)

    // merged preprocessing (x fp16, 4x W fp16, weff+ybias)
    preproc_kernel<<<9217, 256>>>(x, Wq, Wk, Wv, Wout,
                                  Woff1, boff1, Woff2, boff2, bq);   // idx 0

    // q = Wq·x + bq -> g_qh fp16 [B,C,L]; also offset projections g_y
    mma_gemm<<<ggrid, 256, GSMEM>>>(0, 0, 0, bq, nullptr, nullptr);  // idx 1

    // deformable gather (offset computed inline from g_y)
    gridsample_kernel<<<Mb, 256>>>();                                // idx 2

    // k = Wk·xs + bk -> g_kh fp16 [B,C,L]
    mma_gemm<<<ggrid, 256, GSMEM>>>(1, 1, 1, bk, nullptr, nullptr);  // idx 3 (profiled)

    // attention logits + softmax in one kernel -> g_attn
    attn_qk<<<64, 256, QSMEM>>>();

    // v-GEMM with fused attn·V epilogue -> g_oh fp16 [M,C]
    mma_gemm<<<ggrid, 256, GSMEM>>>(1, 2, 2, bv, rpb, nullptr);

    // out = o_pre·Woutᵀ + bout -> d_out [B,L,C]
    mma_gemm<<<ggrid, 256, GSMEM>>>(2, 3, 3, bout, nullptr, out);
}

// round 15
// speedup vs baseline: 1.1238x; 1.1238x over previous
#include <cuda_runtime.h>
#include <cuda_fp16.h>
#include <math.h>
#include <stdint.h>

// Problem constants
#define Bb 4
#define Lb 4096
#define Cb 512
#define Gb 4
#define GCb 128
#define Hb 16
#define HCb 32
#define Mb (Bb*Lb)        // 16384
#define NBg (Bb*Gb)       // 16

// ---------------- scratch (static device globals; no allocation) -------------
__device__ __half g_qh[Bb*Cb*Lb];                  // q fp16 [B,C,L] (attn only)
__device__ __half g_kh[Bb*Cb*Lb];                  // k fp16 [B,C,L] (attn only)
__device__ __half g_xh[Mb*Cb];                     // x fp16      [M,C]
__device__ __half g_sh[Mb*Cb];                     // xs fp16     [M,C]
__device__ __half g_oh[Mb*Cb];                     // o_pre fp16  [M,C]
__device__ __half g_w16[4][Cb*Cb];                 // weights fp16
__device__ float g_weff[GCb*5];
__device__ float g_ybias[Gb*5];
__device__ float g_bias2[2];
__device__ float g_y[NBg*5*Lb];                    // offset conv projections
__device__ float g_logits[8*64*HCb*HCb];           // 8 L-chunk qk partials
__device__ float g_attn[64*HCb*HCb];               // softmaxed, TRANSPOSED [bh][j][i]

// ---------------- small helpers ----------------------------------------------
__device__ __forceinline__ uint32_t smem_to_u32(const void* p) {
    uint32_t a;
    asm("{ .reg .u64 t; cvta.to.shared.u64 t, %1; cvt.u32.u64 %0, t; }" : "=r"(a) : "l"(p));
    return a;
}

#define LDM4(r, a) \
    asm volatile("ldmatrix.sync.aligned.m8n8.x4.shared.b16 {%0,%1,%2,%3}, [%4];" \
        : "=r"((r)[0]), "=r"((r)[1]), "=r"((r)[2]), "=r"((r)[3]) : "r"(a))

__device__ __forceinline__ void mma16816(float* d, const uint32_t* a, const uint32_t* b) {
    asm volatile("mma.sync.aligned.m16n8k16.row.col.f32.f16.f16.f32 "
        "{%0,%1,%2,%3}, {%4,%5,%6,%7}, {%8,%9}, {%0,%1,%2,%3};"
        : "+f"(d[0]), "+f"(d[1]), "+f"(d[2]), "+f"(d[3])
        : "r"(a[0]), "r"(a[1]), "r"(a[2]), "r"(a[3]), "r"(b[0]), "r"(b[1]));
}

__device__ __forceinline__ void cp_async16(uint32_t dst, const void* src) {
    asm volatile("cp.async.cg.shared.global [%0], [%1], 16;" :: "r"(dst), "l"(src));
}
#define CP_COMMIT()  asm volatile("cp.async.commit_group;" ::: "memory")
#define CP_WAIT(n)   asm volatile("cp.async.wait_group %0;" :: "n"(n) : "memory")

__device__ __forceinline__ uint32_t swz(uint32_t off) { return off ^ ((off >> 3) & 0x70); }

// ---------------- fused offset-conv weight precompute + ybias ----------------
__global__ void weff_kernel(const float* __restrict__ Woff1,
                            const float* __restrict__ boff1,
                            const float* __restrict__ Woff2,
                            const float* __restrict__ boff2,
                            const float* __restrict__ bq)
{
    int i = threadIdx.x;
    if (i < GCb*5) {
        int dp = i / 5, t = i % 5;
        float s = 0.f;
        #pragma unroll 4
        for (int d = 0; d < GCb; d++)
            s += Woff2[d] * Woff1[(d*GCb + dp)*5 + t];
        g_weff[i] = s;
    }
    if (i == 0) {
        float s = boff2[0];
        for (int d = 0; d < GCb; d++) s += Woff2[d]*boff1[d];
        g_bias2[0] = s;
        g_bias2[1] = boff2[0];
    }
    __syncthreads();   // g_weff visible block-wide
    if (i < Gb*5) {
        int g = i / 5, t = i % 5;
        float s = 0.f;
        for (int d = 0; d < GCb; d++)
            s += g_weff[d*5 + t] * bq[g*GCb + d];
        g_ybias[i] = s;
    }
}

// ---------------- fp16 converters ---------------------------------------------
__global__ void convert_x(const float* __restrict__ x)
{
    size_t i = (size_t)blockIdx.x*256 + threadIdx.x;   // Mb*Cb/4 items
    float4 v = ((const float4*)x)[i];
    __half2 p0; p0.x = __float2half(v.x); p0.y = __float2half(v.y);
    __half2 p1; p1.x = __float2half(v.z); p1.y = __float2half(v.w);
    ((__half2*)g_xh)[2*i]   = p0;
    ((__half2*)g_xh)[2*i+1] = p1;
}

__global__ void convert_w_all(const float* __restrict__ W0, const float* __restrict__ W1,
                              const float* __restrict__ W2, const float* __restrict__ W3)
{
    const int w = blockIdx.y;
    const float* W = (w==0) ? W0 : (w==1) ? W1 : (w==2) ? W2 : W3;
    size_t i = (size_t)blockIdx.x*256 + threadIdx.x;   // Cb*Cb/4 items
    float4 v = ((const float4*)W)[i];
    __half2 p0; p0.x = __float2half(v.x); p0.y = __float2half(v.y);
    __half2 p1; p1.x = __float2half(v.z); p1.y = __float2half(v.w);
    ((__half2*)g_w16[w])[2*i]   = p0;
    ((__half2*)g_w16[w])[2*i+1] = p1;
}

// ---------------- mma.sync GEMM: out[m,n] = sum_k A[m,k]*W[n,k] --------------
// A,W fp16. CTA tile 128x128, 256 thr (8 warps, 2x4), warp tile 64x32,
// K chunks of 64, 3-stage cp.async ring, ONE sync/chunk, 2 CTAs/SM.
// o_sel: 0 = g_qh fp16 [B,C,L]+bias AND offset-conv projections y -> g_y;
//        1 = g_kh fp16 [B,C,L]+bias;
//        2 = fused attn·V epilogue -> g_oh fp16 [M,C];
//        3 = row-major [M,C] + bias (final output).
#define KCHUNK 64
#define TILE_B 16384            // one 128x64 fp16 tile
#define STAGE_B (2*TILE_B)      // A, W

__global__ __launch_bounds__(256, 2)
void mma_gemm(int a_sel, int w_idx, int o_sel,
              const float* __restrict__ bias,
              const float* __restrict__ rpb,
              float* __restrict__ Or)
{
    extern __shared__ __align__(1024) char smem[];
    const uint32_t su = smem_to_u32(smem);
    const int tid = threadIdx.x;
    const int wid = tid >> 5, lane = tid & 31;
    const int bm = blockIdx.x, bn = blockIdx.y;

    const __half* A = (a_sel==0) ? g_xh : (a_sel==1) ? g_sh : g_oh;
    const __half* srcs[2] = {A, g_w16[w_idx]};

    // ---- stage loader: 2 tiles x 1024 16B-chunks, 8 cp.async per thread ----
    auto load_stage = [&](int s, int buf) {
        const int k0 = s*KCHUNK;
        #pragma unroll
        for (int t = 0; t < 2; t++) {
            const __half* src = srcs[t];
            const int rbase = ((t == 0) ? bm : bn) * 128;
            const uint32_t tb = su + buf*STAGE_B + t*TILE_B;
            #pragma unroll
            for (int i = 0; i < 4; i++) {
                int cid = tid + i*256;
                int row = cid >> 3, cu = cid & 7;
                const void* g = src + (size_t)(rbase + row)*Cb + k0 + cu*8;
                cp_async16(tb + swz((uint32_t)(row*128 + cu*16)), g);
            }
        }
        CP_COMMIT();
    };

    // ---- per-lane fragment addressing (warp tile 64x32) ----
    const int warp_m = wid >> 2;          // 0..1 (64 rows each)
    const int warp_n = wid & 3;           // 0..3 (32 cols each)
    const int lr = lane & 7;
    uint32_t aRowOff[4];
    #pragma unroll
    for (int mt = 0; mt < 4; mt++)
        aRowOff[mt] = (uint32_t)((warp_m*64 + mt*16 + lr + ((lane>>3)&1)*8) * 128);
    const uint32_t aC = (uint32_t)(lane >> 4);
    uint32_t bRowOff[2];
    #pragma unroll
    for (int nh = 0; nh < 2; nh++)
        bRowOff[nh] = (uint32_t)((warp_n*32 + nh*16 + lr + (lane>>4)*8) * 128);
    const uint32_t bC = (uint32_t)((lane >> 3) & 1);

    float acc[4][4][4];
    #pragma unroll
    for (int mt = 0; mt < 4; mt++)
        #pragma unroll
        for (int nt = 0; nt < 4; nt++)
            #pragma unroll
            for (int c = 0; c < 4; c++) acc[mt][nt][c] = 0.f;

    // ---- 3-stage ring: buffers s%3; one barrier per chunk ----
    load_stage(0, 0);
    load_stage(1, 1);

    #pragma unroll 1
    for (int kc = 0; kc < 8; kc++) {
        if (kc < 7) { CP_WAIT(1); } else { CP_WAIT(0); }
        __syncthreads();
        if (kc + 2 < 8) load_stage(kc + 2, (kc + 2) % 3);

        const uint32_t sb = su + (uint32_t)(kc % 3)*STAGE_B;
        #pragma unroll
        for (int ks = 0; ks < 4; ks++) {
            uint32_t ah[4][4], bf[2][4];
            #pragma unroll
            for (int mt = 0; mt < 4; mt++) {
                uint32_t off = swz(aRowOff[mt] + (ks*2 + aC)*16);
                LDM4(ah[mt], sb + off);
            }
            #pragma unroll
            for (int nh = 0; nh < 2; nh++) {
                uint32_t off = swz(bRowOff[nh] + (ks*2 + bC)*16);
                LDM4(bf[nh], sb + TILE_B + off);
            }
            #pragma unroll
            for (int mt = 0; mt < 4; mt++)
                #pragma unroll
                for (int nt = 0; nt < 4; nt++)
                    mma16816(acc[mt][nt], ah[mt], &bf[nt >> 1][(nt & 1)*2]);
        }
    }
    __syncthreads();   // all compute done before epilogue reuses smem

    const int g = lane >> 2, t4 = lane & 3;

    if (o_sel == 2) {
        // ======== fused attn·V epilogue (4 heads per CTA) ========
        float* v_s  = (float*)smem;                 // [128 c][129] floats
        float* at_s = (float*)smem + 128*129;       // attn_t 4 heads x 32 x 32
        #pragma unroll
        for (int mt = 0; mt < 4; mt++)
            #pragma unroll
            for (int nt = 0; nt < 4; nt++)
                #pragma unroll
                for (int c = 0; c < 4; c++) {
                    int ml = warp_m*64 + mt*16 + g + (c >> 1)*8;
                    int nl = warp_n*32 + nt*8 + 2*t4 + (c & 1);
                    v_s[nl*129 + ml] = acc[mt][nt][c];
                }
        const int bidx  = (bm*128) >> 12;
        const int lbase = (bm*128) & 4095;
        const float* asrc = g_attn + ((size_t)bidx*16 + bn*4)*1024;
        for (int i = tid; i < 4096; i += 256) at_s[i] = asrc[i];
        __syncthreads();
        #pragma unroll 1
        for (int r = 0; r < 64; r++) {
            int idx = tid + r*256;
            int c = idx >> 7, l = idx & 127;
            v_s[c*129 + l] += bias[bn*128 + c]
                            + rpb[(size_t)(bn*128 + c)*Lb + lbase + l];
        }
        __syncthreads();
        #pragma unroll 1
        for (int task = wid; task < 64; task += 8) {
            int lb = task >> 2, hh = task & 3;
            float areg[32];
            #pragma unroll
            for (int j = 0; j < 32; j++)
                areg[j] = at_s[(hh*32 + j)*32 + lane];   // attn_t[j][i=lane]
            #pragma unroll
            for (int ll = 0; ll < 8; ll++) {
                int l = lb*8 + ll;
                float o = 0.f;
                #pragma unroll
                for (int j = 0; j < 32; j++)
                    o += areg[j] * v_s[(hh*32 + j)*129 + l];
                size_t oidx = ((size_t)bidx*Lb + lbase + l)*Cb + bn*128 + hh*32 + lane;
                g_oh[oidx] = __float2half(o);
            }
        }
        return;
    }

    // ======== standard epilogue: stage warp tile (64x32) into padded smem ====
    float* sacc = (float*)smem + (size_t)wid*(64*33);
    #pragma unroll
    for (int mt = 0; mt < 4; mt++)
        #pragma unroll
        for (int nt = 0; nt < 4; nt++)
            #pragma unroll
            for (int c = 0; c < 4; c++) {
                int ml = mt*16 + g + (c >> 1)*8;
                int nl = nt*8 + 2*t4 + (c & 1);
                sacc[ml*33 + nl] = acc[mt][nt][c];
            }
    __syncwarp();

    const int bidx = (bm*128) >> 12;
    const int lbase = (bm*128) & 4095;

    if (o_sel == 0) {
        // q fp16 store (bias fused)
        const int lwarp = lbase + warp_m*64;
        #pragma unroll 1
        for (int n = 0; n < 32; n++) {
            const int nglob = bn*128 + warp_n*32 + n;
            const float bv = bias[nglob];
            #pragma unroll
            for (int h2 = 0; h2 < 2; h2++) {
                const int ml = h2*32 + lane;
                g_qh[((size_t)bidx*Cb + nglob)*Lb + lwarp + ml]
                    = __float2half(sacc[ml*33 + n] + bv);
            }
        }
        // ---- offset-conv projections: y[t][l] = sum_d Weff[d,t]*qraw[d,l] ----
        float* weff_s = (float*)smem + 8*64*33;     // 640 floats
        float* py     = weff_s + 640;               // 8 warps x 5 x 64
        for (int i = tid; i < 640; i += 256) weff_s[i] = g_weff[i];
        __syncthreads();
        #pragma unroll
        for (int h2 = 0; h2 < 2; h2++) {
            const int ml = h2*32 + lane;
            float y0=0.f, y1=0.f, y2=0.f, y3=0.f, y4=0.f;
            #pragma unroll 4
            for (int d = 0; d < 32; d++) {
                float qv = sacc[ml*33 + d];
                const float* wr = weff_s + (warp_n*32 + d)*5;
                y0 += qv*wr[0]; y1 += qv*wr[1]; y2 += qv*wr[2];
                y3 += qv*wr[3]; y4 += qv*wr[4];
            }
            float* p = py + wid*320 + ml;
            p[0] = y0; p[64] = y1; p[128] = y2; p[192] = y3; p[256] = y4;
        }
        __syncthreads();
        // reduce over warp_n (4 partials) + ybias, write g_y
        for (int idx = tid; idx < 640; idx += 256) {
            int wm = idx / 320;
            int r  = idx % 320;              // t*64 + ml
            int t  = r >> 6;
            float y = py[(wm*4+0)*320 + r] + py[(wm*4+1)*320 + r]
                    + py[(wm*4+2)*320 + r] + py[(wm*4+3)*320 + r]
                    + g_ybias[bn*5 + t];
            int l = lbase + wm*64 + (r & 63);
            g_y[((size_t)(bidx*Gb + bn)*5 + t)*Lb + l] = y;
        }
        return;
    }

    if (o_sel == 1) {
        const int lwarp = lbase + warp_m*64;
        #pragma unroll 1
        for (int n = 0; n < 32; n++) {
            const int nglob = bn*128 + warp_n*32 + n;
            const float bv = bias[nglob];
            #pragma unroll
            for (int h2 = 0; h2 < 2; h2++) {
                const int ml = h2*32 + lane;
                g_kh[((size_t)bidx*Cb + nglob)*Lb + lwarp + ml]
                    = __float2half(sacc[ml*33 + n] + bv);
            }
        }
    } else {
        const int nglob = bn*128 + warp_n*32 + lane;
        const float bv = bias[nglob];
        #pragma unroll 1
        for (int ml = 0; ml < 64; ml++) {
            const int m = bm*128 + warp_m*64 + ml;
            Or[(size_t)m*Cb + nglob] = sacc[ml*33 + lane] + bv;
        }
    }
}

// ---------------- 1-D bilinear grid sample w/ inline offset, 2 positions/blk -
__global__ __launch_bounds__(256)
void gridsample_kernel()
{
    const int blk = blockIdx.x;        // 8192 blocks, 2 positions each
    const int b   = blk >> 11;
    const int l0  = (blk & 2047) * 2;

    const int c2 = threadIdx.x;        // half2 index; channels 2*c2, 2*c2+1
    const int g  = c2 >> 6;            // warp-uniform
    const float* yb = g_y + (size_t)(b*Gb + g)*5*Lb;

    #pragma unroll
    for (int u = 0; u < 2; u++) {
        const int l = l0 + u;
        float accf;
        if (l >= 4) {
            accf = g_bias2[0];
            #pragma unroll
            for (int t = 0; t < 5; t++) accf += yb[(size_t)t*Lb + l - 4 + t];
        } else if (l >= 2) {
            accf = g_bias2[0];
            for (int t = 4 - l; t < 5; t++) accf += yb[(size_t)t*Lb + l - 4 + t];
        } else {
            accf = g_bias2[1];
        }
        const float off = tanhf(accf) * 5.0f;

        const float vgrid = (float)l + off;
        const float gy = 2.0f * vgrid / (float)(Lb + 4 - 1) - 1.0f;
        const float iy = ((gy + 1.0f) * (float)Lb - 1.0f) * 0.5f;
        const float fi0 = floorf(iy);
        const float w1 = iy - fi0;
        const int i0 = (int)fi0;
        const int i1 = i0 + 1;

        float2 f0 = make_float2(0.f, 0.f), f1 = make_float2(0.f, 0.f);
        if (i0 >= 0 && i0 < Lb)
            f0 = __half22float2(((const __half2*)(g_xh + ((size_t)b*Lb + i0)*Cb))[c2]);
        if (i1 >= 0 && i1 < Lb)
            f1 = __half22float2(((const __half2*)(g_xh + ((size_t)b*Lb + i1)*Cb))[c2]);
        const float w0 = 1.f - w1;
        __half2 r;
        r.x = __float2half(f0.x*w0 + f1.x*w1);
        r.y = __float2half(f0.y*w0 + f1.y*w1);
        ((__half2*)(g_sh + ((size_t)b*Lb + l)*Cb))[c2] = r;
    }
}

// ---------------- attention logits via mma.sync -------------------------------
// logits[i][j] = sum_l q[i,l]*k[j,l]. Per block: 4 warps x 128 L each (2 chunks
// of 64); per-warp 32x32 fp32 partial in regs; smem cross-warp reduce.
#define QK_TILE 4096    // bytes of one 32x64 fp16 tile
__global__ __launch_bounds__(128)
void attn_qk()
{
    extern __shared__ __align__(1024) char qsmem[];
    const uint32_t su = smem_to_u32(qsmem);
    const int tid = threadIdx.x;
    const int wid = tid >> 5, lane = tid & 31;
    const int lc = blockIdx.x;            // 0..7
    const int bh = blockIdx.y;            // 0..63
    const int b = bh >> 4, h = bh & 15;
    const size_t base = ((size_t)b*Cb + h*HCb) * Lb;
    const __half* qb = g_qh + base;
    const __half* kb = g_kh + base;
    const int l0 = lc*512 + wid*128;

    const uint32_t wbase = su + (uint32_t)wid*(4*QK_TILE);   // 16KB per warp

    auto load_chunk = [&](int ch) {
        const int lo = l0 + ch*64;
        const uint32_t tb = wbase + (uint32_t)ch*(2*QK_TILE);
        #pragma unroll
        for (int i = 0; i < 8; i++) {
            int cid = lane + i*32;
            int row = cid >> 3, cu = cid & 7;
            uint32_t so = swz((uint32_t)(row*128 + cu*16));
            cp_async16(tb + so,           qb + (size_t)row*Lb + lo + cu*8);
            cp_async16(tb + QK_TILE + so, kb + (size_t)row*Lb + lo + cu*8);
        }
        CP_COMMIT();
    };

    const int lr = lane & 7;
    uint32_t aRowOff[2], bRowOff[2];
    #pragma unroll
    for (int mt = 0; mt < 2; mt++)
        aRowOff[mt] = (uint32_t)((mt*16 + lr + ((lane>>3)&1)*8) * 128);
    const uint32_t aC = (uint32_t)(lane >> 4);
    #pragma unroll
    for (int nh = 0; nh < 2; nh++)
        bRowOff[nh] = (uint32_t)((nh*16 + lr + (lane>>4)*8) * 128);
    const uint32_t bC = (uint32_t)((lane >> 3) & 1);

    float acc[2][4][4];
    #pragma unroll
    for (int mt = 0; mt < 2; mt++)
        #pragma unroll
        for (int nt = 0; nt < 4; nt++)
            #pragma unroll
            for (int c = 0; c < 4; c++) acc[mt][nt][c] = 0.f;

    load_chunk(0);
    load_chunk(1);

    #pragma unroll
    for (int ch = 0; ch < 2; ch++) {
        if (ch == 0) { CP_WAIT(1); } else { CP_WAIT(0); }
        __syncwarp();
        const uint32_t tb = wbase + (uint32_t)ch*(2*QK_TILE);
        #pragma unroll
        for (int ks = 0; ks < 4; ks++) {
            uint32_t af[2][4], bf[2][4];
            #pragma unroll
            for (int mt = 0; mt < 2; mt++)
                LDM4(af[mt], tb + swz(aRowOff[mt] + (ks*2 + aC)*16));
            #pragma unroll
            for (int nh = 0; nh < 2; nh++)
                LDM4(bf[nh], tb + QK_TILE + swz(bRowOff[nh] + (ks*2 + bC)*16));
            #pragma unroll
            for (int mt = 0; mt < 2; mt++)
                #pragma unroll
                for (int nt = 0; nt < 4; nt++)
                    mma16816(acc[mt][nt], af[mt], &bf[nt >> 1][(nt & 1)*2]);
        }
    }

    // write per-warp partial into its own smem region (canonical 32x32)
    float* part = (float*)(qsmem + (size_t)wid*(4*QK_TILE));
    const int g = lane >> 2, t4 = lane & 3;
    #pragma unroll
    for (int mt = 0; mt < 2; mt++)
        #pragma unroll
        for (int nt = 0; nt < 4; nt++)
            #pragma unroll
            for (int c = 0; c < 4; c++) {
                int ml = mt*16 + g + (c >> 1)*8;
                int nl = nt*8 + 2*t4 + (c & 1);
                part[ml*32 + nl] = acc[mt][nt][c];
            }
    __syncthreads();

    float* O = g_logits + ((size_t)lc*64 + bh)*1024;
    for (int i = tid; i < 1024; i += 128) {
        float v = ((float*)(qsmem           ))[i]
                + ((float*)(qsmem + 4*QK_TILE))[i]
                + ((float*)(qsmem + 8*QK_TILE))[i]
                + ((float*)(qsmem + 12*QK_TILE))[i];
        O[i] = v;
    }
}

// ---------------- softmax (sums partials; writes TRANSPOSED attn) ------------
__global__ __launch_bounds__(1024)
void attn_softmax()
{
    const int bh = blockIdx.x;
    const int tx = threadIdx.x;    // j
    const int ty = threadIdx.y;    // i
    const int idx = ty*32 + tx;
    float v = 0.f;
    #pragma unroll
    for (int p = 0; p < 8; p++) v += g_logits[((size_t)p*64 + bh)*1024 + idx];
    v *= 0.044194173824159216f;   // 512^-0.5
    float mx = v;
    #pragma unroll
    for (int s = 16; s > 0; s >>= 1) mx = fmaxf(mx, __shfl_xor_sync(0xffffffffu, mx, s));
    float e = expf(v - mx);
    float sum = e;
    #pragma unroll
    for (int s = 16; s > 0; s >>= 1) sum += __shfl_xor_sync(0xffffffffu, sum, s);
    g_attn[(size_t)bh*1024 + tx*32 + ty] = e / sum;   // transposed [j][i]
}

// ---------------- launcher ---------------------------------------------------
extern "C" void kernel_launch(void* const* d_in, const int* in_sizes, int n_in,
                              void* d_out, int out_size)
{
    const float* x     = (const float*)d_in[0];
    const float* Wq    = (const float*)d_in[1];
    const float* bq    = (const float*)d_in[2];
    const float* Wk    = (const float*)d_in[3];
    const float* bk    = (const float*)d_in[4];
    const float* Wv    = (const float*)d_in[5];
    const float* bv    = (const float*)d_in[6];
    const float* Woff1 = (const float*)d_in[7];
    const float* boff1 = (const float*)d_in[8];
    const float* Woff2 = (const float*)d_in[9];
    const float* boff2 = (const float*)d_in[10];
    const float* rpb   = (const float*)d_in[11];
    const float* Wout  = (const float*)d_in[12];
    const float* bout  = (const float*)d_in[13];
    float* out = (float*)d_out;

    const int GSMEM = 3*STAGE_B;       // 98304 (>= all GEMM epilogues)
    const int QSMEM = 4*4*QK_TILE;     // 65536
    cudaFuncSetAttribute(mma_gemm, cudaFuncAttributeMaxDynamicSharedMemorySize, GSMEM);
    cudaFuncSetAttribute(attn_qk,  cudaFuncAttributeMaxDynamicSharedMemorySize, QSMEM);

    dim3 ggrid(Mb/128, Cb/128);    // (128, 4)

    convert_x<<<Mb*Cb/4/256, 256>>>(x);                             // idx 0
    convert_w_all<<<dim3(Cb*Cb/4/256, 4), 256>>>(Wq, Wk, Wv, Wout); // idx 1
    weff_kernel<<<1, 640>>>(Woff1, boff1, Woff2, boff2, bq);        // idx 2

    // q = Wq·x + bq -> g_qh fp16 [B,C,L]; also offset projections g_y
    mma_gemm<<<ggrid, 256, GSMEM>>>(0, 0, 0, bq, nullptr, nullptr); // idx 3 (profiled)

    // deformable gather (offset computed inline from g_y), 2 positions/block
    gridsample_kernel<<<Mb/2, 256>>>();

    // k = Wk·xs + bk -> g_kh fp16 [B,C,L]
    mma_gemm<<<ggrid, 256, GSMEM>>>(1, 1, 1, bk, nullptr, nullptr);

    // attention logits (tensor-core) + softmax
    attn_qk<<<dim3(8, 64), 128, QSMEM>>>();
    attn_softmax<<<64, dim3(32, 32)>>>();

    // v-GEMM with fused attn·V epilogue -> g_oh fp16 [M,C]
    mma_gemm<<<ggrid, 256, GSMEM>>>(1, 2, 2, bv, rpb, nullptr);

    // out = o_pre·Woutᵀ + bout -> d_out [B,L,C]
    mma_gemm<<<ggrid, 256, GSMEM>>>(2, 3, 3, bout, nullptr, out);
}